// round 12
// baseline (speedup 1.0000x reference)
#include <cuda_runtime.h>
#include <math_constants.h>

// GaussianVector_box — single-kernel store streamer, params amortized 4x.
// 256-thread CTAs, FOUR boxes per CTA (64-thread slice per box); each thread
// owns four float4s per row -> 8x STG.128 per thread, param math computed once
// per 128 output bytes. Compute/store interleaved to cap register pressure.
// Output: [vector_x (B*N*1024)] ++ [vector_y (B*N*1024)], f32, 268 MB writes.

#define OUT_W 1024
#define OUT_H 1024

__device__ __forceinline__ float4 gauss4(float c0, float ul, float br,
                                         float ctr, float k)
{
    float4 v = make_float4(0.f, 0.f, 0.f, 0.f);
    if ((c0 + 3.0f) >= ul && c0 < br) {
        #pragma unroll
        for (int j = 0; j < 4; ++j) {
            float p = c0 + (float)j;
            if (p >= ul && p < br) {
                float d = p - ctr;
                float e = __expf(d * d * k);
                if (j == 0) v.x = e; else if (j == 1) v.y = e;
                else if (j == 2) v.z = e; else v.w = e;
            }
        }
    }
    return v;
}

__global__ __launch_bounds__(256, 8)
void gv_box_kernel(const float* __restrict__ centers,
                   const float* __restrict__ whs,
                   float* __restrict__ out_x,
                   float* __restrict__ out_y)
{
    const int bn = (blockIdx.x << 2) + (threadIdx.x >> 6);  // 4 boxes per CTA
    const int t  = threadIdx.x & 63;                        // 0..63 within box

    // Broadcast loads (uniform address per 64-thread slice -> L1/L2 hit).
    const float2 c  = __ldg(((const float2*)centers) + bn);
    const float2 wh = __ldg(((const float2*)whs) + bn);

    // ks = floor(W/2)*2 - 1 ; r = (ks-1)/2 = floor(W/2) - 1 (exact)
    const float rw = floorf(wh.x * 0.5f) - 1.0f;
    const float rh = floorf(wh.y * 0.5f) - 1.0f;
    // s = floor(r/3), exact for integer r via the +0.5 trick (no IEEE div)
    const float sw = floorf((rw + 0.5f) * (1.0f / 3.0f));
    const float sh = floorf((rh + 0.5f) * (1.0f / 3.0f));

    const bool zero_box = (c.x + c.y + wh.x + wh.y) == 0.0f;

    // SCALE = 1 ; astype(int32) truncates toward zero
    const float x = truncf(c.x);
    const float y = truncf(c.y);

    float ul0 = x - rw, ul1 = y - rh;
    float br0 = x + rw + 1.0f, br1 = y + rh + 1.0f;

    const bool in_ul = (ul0 >= 0.0f) & (ul0 <= (float)OUT_W) &
                       (ul1 >= 0.0f) & (ul1 <= (float)OUT_H);
    const bool in_br = (br0 >= 0.0f) & (br0 <= (float)OUT_W) &
                       (br1 >= 0.0f) & (br1 <= (float)OUT_H);

    const bool active = (!zero_box) & (sw != 0.0f) & (sh != 0.0f) & (in_ul | in_br);

    if (!active) {   // empty windows -> all lanes write zero, no exp evaluated
        ul0 = CUDART_INF_F;  br0 = -CUDART_INF_F;
        ul1 = CUDART_INF_F;  br1 = -CUDART_INF_F;
    }

    // -1/(2 sigma^2) via fast reciprocal (only consumed inside valid windows)
    const float kx = __fdividef(-0.5f, sw * sw);
    const float ky = __fdividef(-0.5f, sh * sh);

    float4* px = ((float4*)(out_x + (size_t)bn * OUT_W)) + t;
    float4* py = ((float4*)(out_y + (size_t)bn * OUT_H)) + t;

    const float cbase = (float)(t << 2);

    // Interleave compute+store (one float4 live at a time -> low reg pressure).
    #pragma unroll
    for (int i = 0; i < 4; ++i) {
        const float ci = cbase + (float)(i * 256);          // 64 float4s per seg
        __stcs(px + (i << 6), gauss4(ci, ul0, br0, x, kx));
    }
    #pragma unroll
    for (int i = 0; i < 4; ++i) {
        const float ci = cbase + (float)(i * 256);
        __stcs(py + (i << 6), gauss4(ci, ul1, br1, y, ky));
    }
}

extern "C" void kernel_launch(void* const* d_in, const int* in_sizes, int n_in,
                              void* d_out, int out_size)
{
    const float* centers = (const float*)d_in[0];  // [B,N,2]
    const float* whs     = (const float*)d_in[1];  // [B,N,2]
    float* out = (float*)d_out;

    const int BN = in_sizes[0] / 2;                // 128*256 = 32768
    float* out_x = out;
    float* out_y = out + (size_t)BN * OUT_W;

    gv_box_kernel<<<BN / 4, 256>>>(centers, whs, out_x, out_y);
}